// round 8
// baseline (speedup 1.0000x reference)
#include <cuda_runtime.h>
#include <cuda_bf16.h>
#include <math.h>
#include <stdint.h>

#define L_    13
#define B_    16
#define S_    512
#define H_    768
#define QL    20
#define DL    492
#define NB    11
#define HID   5
#define NALL  14
#define KC    64            // K floats per chunk (256B fp32, 128B bf16)
#define NCH   12            // 768 / 64
#define NDCH  4
#define EPSF  1e-8f
#define THR   512           // 8 consumer + 8 producer warps
#define NWORK (L_ * B_ * NDCH)   // 832

__device__ int g_hist[L_ * B_ * NDCH * NB];
__device__ int g_arrive = 0;

// smem: 2-stage ring of (A 4KB + B 16KB), then norms/hist.
#define STAGE_BYTES 20480
#define SM_DN 40960          // 128 floats
#define SM_QN 41472          // 20 floats
#define SM_HI 41552          // 11 ints
#define SM_SZ 41600

#define SWZ(x) ((x) ^ (((x) >> 3) & 0x70))

// named barrier ids (0 reserved for __syncthreads)
#define FULL0  1
#define EMPTY0 3

__device__ __forceinline__ void bsync(int id) {
    asm volatile("bar.sync %0, %1;" :: "r"(id), "n"(THR) : "memory");
}
__device__ __forceinline__ void barrive(int id) {
    asm volatile("bar.arrive %0, %1;" :: "r"(id), "n"(THR) : "memory");
}
__device__ __forceinline__ uint32_t sm_u32(const void* p) {
    uint32_t a;
    asm("{.reg .u64 t; cvta.to.shared.u64 t, %1; cvt.u32.u64 %0, t;}"
        : "=r"(a) : "l"(p));
    return a;
}
__device__ __forceinline__ uint32_t bfpack(float lo, float hi) {
    uint32_t r;
    asm("cvt.rn.bf16x2.f32 %0, %1, %2;" : "=r"(r) : "f"(hi), "f"(lo));
    return r;
}
__device__ __forceinline__ void ldmat4(uint32_t& r0, uint32_t& r1,
                                       uint32_t& r2, uint32_t& r3, uint32_t a) {
    asm volatile("ldmatrix.sync.aligned.m8n8.x4.shared.b16 {%0,%1,%2,%3}, [%4];"
                 : "=r"(r0), "=r"(r1), "=r"(r2), "=r"(r3) : "r"(a));
}
__device__ __forceinline__ void mma16816(float* c, uint32_t a0, uint32_t a1,
                                         uint32_t a2, uint32_t a3,
                                         uint32_t b0, uint32_t b1) {
    asm volatile(
        "mma.sync.aligned.m16n8k16.row.col.f32.bf16.bf16.f32 "
        "{%0,%1,%2,%3}, {%4,%5,%6,%7}, {%8,%9}, {%0,%1,%2,%3};"
        : "+f"(c[0]), "+f"(c[1]), "+f"(c[2]), "+f"(c[3])
        : "r"(a0), "r"(a1), "r"(a2), "r"(a3), "r"(b0), "r"(b1));
}

__global__ __launch_bounds__(THR, 1)
void cedr_fused_kernel(const float* __restrict__ hs,
                       const float* __restrict__ W_hist,
                       const float* __restrict__ b_hist,
                       const float* __restrict__ W_comb,
                       const float* __restrict__ b_comb,
                       float* __restrict__ out) {
    __shared__ __align__(1024) char sm[SM_SZ];
    const int tid  = threadIdx.x;
    const int lane = tid & 31;
    const int wid  = tid >> 5;

    // ======================= FINALIZER CTA =======================
    if (blockIdx.x == NWORK) {
        if (tid == 0) {
            while (atomicCAS(&g_arrive, NWORK, 0) != NWORK) {}
            __threadfence();
        }
        __syncthreads();
        const float inv_n = 1.0f / (float)(QL * DL);
        if (wid < B_) {
            const int b = wid;
            float sum = 0.f;
            const float* cls = hs + (size_t)(12 * B_ + b) * S_ * H_;
            for (int h = lane; h < H_; h += 32) sum += cls[h] * W_comb[h];
            for (int i = lane; i < NALL * NB; i += 32) {
                int lp = i / NB, n = i % NB;
                int lsrc = (lp == 0) ? 0 : lp - 1;
                int cnt = 0;
                #pragma unroll
                for (int d = 0; d < NDCH; d++)
                    cnt += g_hist[((lsrc * B_ + b) * NDCH + d) * NB + n];
                float coef = 0.f;
                #pragma unroll
                for (int o = 0; o < HID; o++)
                    coef += W_hist[o * NB + n] * W_comb[H_ + lp * HID + o];
                sum += (float)cnt * inv_n * coef;
            }
            if (lane == 0) {
                float cst = b_comb[0];
                for (int lp = 0; lp < NALL; lp++)
                    #pragma unroll
                    for (int o = 0; o < HID; o++)
                        cst += b_hist[o] * W_comb[H_ + lp * HID + o];
                sum += cst;
            }
            #pragma unroll
            for (int o = 16; o > 0; o >>= 1)
                sum += __shfl_xor_sync(0xffffffffu, sum, o);
            if (lane == 0) out[b] = sum;
        }
        return;
    }

    // ======================= WORKER CTA =======================
    const int id = blockIdx.x;
    const int dc = id & 3, b = (id >> 2) & 15, l = id >> 6;
    const int dstart = dc * 128;
    const uint32_t smb = sm_u32(sm);
    float* sDn = reinterpret_cast<float*>(sm + SM_DN);
    float* sQn = reinterpret_cast<float*>(sm + SM_QN);
    int*   sHist = reinterpret_cast<int*>(sm + SM_HI);

    if (tid < NB) sHist[tid] = 0;

    if (wid >= 8) {
        // =================== PRODUCER (warps 8..15) ===================
        const int pwid = wid - 8;
        const int c16 = lane & 15;
        const int lane_hi = lane >> 4;
        const int rbase = pwid * 16 + lane_hi * 8;     // D rows rbase..+7
        const float* dbase0 = hs + ((size_t)(l * B_ + b) * S_ + QL) * H_;
        const float* qbase  = hs + (size_t)(l * B_ + b) * S_ * H_;
        const int qr0 = pwid * 4 + lane_hi * 2;        // producer warps 0..4

        float dn2p[8];
        #pragma unroll
        for (int j = 0; j < 8; j++) dn2p[j] = 0.f;
        float qn2p[2] = {0.f, 0.f};
        float4 dv[8], qv[2];

        for (int c = 0; c < NCH; c++) {
            const int s = c & 1;
            // LDG for chunk c issues BEFORE the empty wait (reg lookahead)
            #pragma unroll
            for (int j = 0; j < 8; j++) {
                int dgl = dstart + rbase + j;
                dv[j] = (dgl < DL)
                    ? __ldcs(reinterpret_cast<const float4*>(
                          dbase0 + (size_t)dgl * H_ + c * KC + c16 * 4))
                    : make_float4(0.f, 0.f, 0.f, 0.f);
            }
            if (pwid < 5) {
                #pragma unroll
                for (int j = 0; j < 2; j++)
                    qv[j] = *reinterpret_cast<const float4*>(
                        qbase + (size_t)(qr0 + j) * H_ + c * KC + c16 * 4);
            }
            if (c >= 2) bsync(EMPTY0 + s);             // stage free?

            char* bbase = sm + s * STAGE_BYTES + 4096;
            #pragma unroll
            for (int j = 0; j < 8; j++) {
                dn2p[j] += dv[j].x * dv[j].x + dv[j].y * dv[j].y
                         + dv[j].z * dv[j].z + dv[j].w * dv[j].w;
                uint2 pk;
                pk.x = bfpack(dv[j].x, dv[j].y);
                pk.y = bfpack(dv[j].z, dv[j].w);
                int row = rbase + j;
                *reinterpret_cast<uint2*>(bbase + SWZ(row * 128 + c16 * 8)) = pk;
            }
            if (pwid < 5) {
                char* abase = sm + s * STAGE_BYTES;
                #pragma unroll
                for (int j = 0; j < 2; j++) {
                    qn2p[j] += qv[j].x * qv[j].x + qv[j].y * qv[j].y
                             + qv[j].z * qv[j].z + qv[j].w * qv[j].w;
                    uint2 pk;
                    pk.x = bfpack(qv[j].x, qv[j].y);
                    pk.y = bfpack(qv[j].z, qv[j].w);
                    int row = qr0 + j;
                    *reinterpret_cast<uint2*>(abase + SWZ(row * 128 + c16 * 8)) = pk;
                }
            }
            barrive(FULL0 + s);                        // stage ready
        }

        // norms: reduce across 16-lane groups
        #pragma unroll
        for (int j = 0; j < 8; j++) {
            float v = dn2p[j];
            v += __shfl_xor_sync(0xffffffffu, v, 1);
            v += __shfl_xor_sync(0xffffffffu, v, 2);
            v += __shfl_xor_sync(0xffffffffu, v, 4);
            v += __shfl_xor_sync(0xffffffffu, v, 8);
            if (c16 == 0) sDn[rbase + j] = sqrtf(v);
        }
        if (pwid < 5) {
            #pragma unroll
            for (int j = 0; j < 2; j++) {
                float v = qn2p[j];
                v += __shfl_xor_sync(0xffffffffu, v, 1);
                v += __shfl_xor_sync(0xffffffffu, v, 2);
                v += __shfl_xor_sync(0xffffffffu, v, 4);
                v += __shfl_xor_sync(0xffffffffu, v, 8);
                if (c16 == 0) sQn[qr0 + j] = sqrtf(v);
            }
        }
    } else {
        // =================== CONSUMER (warps 0..7) ===================
        const int mi = wid & 1;
        const int n0 = (wid >> 1) * 32;
        const int mm = lane >> 3, lr = lane & 7;

        float acc[4][4];
        #pragma unroll
        for (int j = 0; j < 4; j++)
            #pragma unroll
            for (int k = 0; k < 4; k++) acc[j][k] = 0.f;

        for (int c = 0; c < NCH; c++) {
            const int s = c & 1;
            bsync(FULL0 + s);                          // wait data

            const uint32_t abase = smb + s * STAGE_BYTES;
            const uint32_t bbase = abase + 4096;
            #pragma unroll
            for (int kk = 0; kk < 4; kk++) {
                const int kb = kk * 32;
                uint32_t a0, a1, a2, a3;
                {
                    int arow = 16 * mi + ((mm & 1) << 3) + lr;
                    int akb  = kb + ((mm >> 1) << 4);
                    ldmat4(a0, a1, a2, a3, abase + SWZ(arow * 128 + akb));
                }
                uint32_t br[8];
                #pragma unroll
                for (int p = 0; p < 2; p++) {
                    int brow = n0 + 16 * p + ((mm >> 1) << 3) + lr;
                    int bkb  = kb + ((mm & 1) << 4);
                    ldmat4(br[4 * p], br[4 * p + 1], br[4 * p + 2], br[4 * p + 3],
                           bbase + SWZ(brow * 128 + bkb));
                }
                #pragma unroll
                for (int j = 0; j < 4; j++)
                    mma16816(acc[j], a0, a1, a2, a3, br[2 * j], br[2 * j + 1]);
            }
            barrive(EMPTY0 + s);                       // stage consumed
        }

        __syncthreads();   // join producers (norms written)

        // epilogue: cosine -> bin -> warp-aggregated histogram
        const int lr4 = lane >> 2, lc = (lane & 3) * 2;
        const int row0 = 16 * mi + lr4, row1 = row0 + 8;
        const float qn0 = (row0 < QL) ? sQn[row0] : 1.f;
        const float qn1 = (row1 < QL) ? sQn[row1] : 1.f;
        #pragma unroll
        for (int j = 0; j < 4; j++) {
            const int col = n0 + 8 * j + lc;
            const float dn0 = sDn[col], dn1 = sDn[col + 1];
            #pragma unroll
            for (int e = 0; e < 4; e++) {
                const int rw  = (e < 2) ? row0 : row1;
                const float qn = (e < 2) ? qn0 : qn1;
                const int cl  = col + (e & 1);
                const float dn = (e & 1) ? dn1 : dn0;
                int idx = -1;
                if (rw < QL && dstart + cl < DL) {
                    float sim = acc[j][e] / fmaxf(qn * dn, EPSF);
                    float t = (sim + 1.0f) * 5.5f;
                    int bi = (int)floorf(t);
                    if (bi >= 0 && bi < NB) idx = bi;
                }
                unsigned m = __match_any_sync(0xffffffffu, idx);
                if (idx >= 0 && lane == (__ffs(m) - 1))
                    atomicAdd(&sHist[idx], __popc(m));
            }
        }
    }

    if (wid >= 8) __syncthreads();   // producers' matching join
    __syncthreads();                 // histogram complete
    if (tid < NB)
        g_hist[((l * B_ + b) * NDCH + dc) * NB + tid] = sHist[tid];
    __threadfence();
    __syncthreads();
    if (tid == 0) atomicAdd(&g_arrive, 1);
}

extern "C" void kernel_launch(void* const* d_in, const int* in_sizes, int n_in,
                              void* d_out, int out_size) {
    const float* hs     = (const float*)d_in[0];
    const float* W_hist = (const float*)d_in[1];
    const float* b_hist = (const float*)d_in[2];
    const float* W_comb = (const float*)d_in[3];
    const float* b_comb = (const float*)d_in[4];
    float* out = (float*)d_out;

    cedr_fused_kernel<<<NWORK + 1, THR>>>(hs, W_hist, b_hist, W_comb, b_comb, out);
}

// round 9
// speedup vs baseline: 1.5800x; 1.5800x over previous
#include <cuda_runtime.h>
#include <cuda_bf16.h>
#include <math.h>
#include <stdint.h>

#define L_    13
#define B_    16
#define S_    512
#define H_    768
#define QL    20
#define DL    492
#define NB    11
#define HID   5
#define NALL  14
#define KC    64            // K floats per chunk (256B/row fp32)
#define NCH   12            // 768 / 64
#define NDCH  4
#define EPSF  1e-8f
#define THR   256
#define NWORK (L_ * B_ * NDCH)   // 832

__device__ int g_hist[L_ * B_ * NDCH * NB];
__device__ int g_arrive = 0;

// dynamic smem: 2 stages of raw fp32 (Q 20x256B @0, D 128x256B @5120)
#define STAGE 37888
#define SM_DN 75776          // 128 floats
#define SM_QN 76288          // 20 floats
#define SM_HI 76368          // 11 ints
#define SM_SZ 76416

extern __shared__ char smdyn[];

// 32B-granule XOR swizzle within a 256B row
__device__ __forceinline__ int swr(int row) { return (row & 7) ^ ((row >> 3) & 1); }
__device__ __forceinline__ uint32_t soff(int row, int col) {
    return (uint32_t)(row * 256 + ((((col >> 5) ^ swr(row)) << 5) | (col & 31)));
}

__device__ __forceinline__ uint32_t bfpack(float lo, float hi) {
    uint32_t r;
    asm("cvt.rn.bf16x2.f32 %0, %1, %2;" : "=r"(r) : "f"(hi), "f"(lo));
    return r;
}
__device__ __forceinline__ void cp16(void* dst, const void* src, bool pred) {
    unsigned s = (unsigned)__cvta_generic_to_shared(dst);
    int n = pred ? 16 : 0;
    asm volatile("cp.async.cg.shared.global [%0], [%1], 16, %2;"
                 :: "r"(s), "l"(src), "r"(n));
}
__device__ __forceinline__ void cp_commit() {
    asm volatile("cp.async.commit_group;");
}
template <int N>
__device__ __forceinline__ void cp_wait() {
    asm volatile("cp.async.wait_group %0;" :: "n"(N));
}
__device__ __forceinline__ void mma16816(float* c, uint32_t a0, uint32_t a1,
                                         uint32_t a2, uint32_t a3,
                                         uint32_t b0, uint32_t b1) {
    asm volatile(
        "mma.sync.aligned.m16n8k16.row.col.f32.bf16.bf16.f32 "
        "{%0,%1,%2,%3}, {%4,%5,%6,%7}, {%8,%9}, {%0,%1,%2,%3};"
        : "+f"(c[0]), "+f"(c[1]), "+f"(c[2]), "+f"(c[3])
        : "r"(a0), "r"(a1), "r"(a2), "r"(a3), "r"(b0), "r"(b1));
}

__global__ __launch_bounds__(THR, 2)
void cedr_fused_kernel(const float* __restrict__ hs,
                       const float* __restrict__ W_hist,
                       const float* __restrict__ b_hist,
                       const float* __restrict__ W_comb,
                       const float* __restrict__ b_comb,
                       float* __restrict__ out) {
    const int tid  = threadIdx.x;
    const int lane = tid & 31;
    const int wid  = tid >> 5;

    // ======================= FINALIZER CTA =======================
    if (blockIdx.x == NWORK) {
        if (tid == 0) {
            while (atomicCAS(&g_arrive, NWORK, 0) != NWORK) {}
            __threadfence();
        }
        __syncthreads();
        const float inv_n = 1.0f / (float)(QL * DL);
        for (int b = wid; b < B_; b += 8) {
            float sum = 0.f;
            const float* cls = hs + (size_t)(12 * B_ + b) * S_ * H_;
            for (int h = lane; h < H_; h += 32) sum += cls[h] * W_comb[h];
            for (int i = lane; i < NALL * NB; i += 32) {
                int lp = i / NB, n = i % NB;
                int lsrc = (lp == 0) ? 0 : lp - 1;
                int cnt = 0;
                #pragma unroll
                for (int d = 0; d < NDCH; d++)
                    cnt += g_hist[((lsrc * B_ + b) * NDCH + d) * NB + n];
                float coef = 0.f;
                #pragma unroll
                for (int o = 0; o < HID; o++)
                    coef += W_hist[o * NB + n] * W_comb[H_ + lp * HID + o];
                sum += (float)cnt * inv_n * coef;
            }
            if (lane == 0) {
                float cst = b_comb[0];
                for (int lp = 0; lp < NALL; lp++)
                    #pragma unroll
                    for (int o = 0; o < HID; o++)
                        cst += b_hist[o] * W_comb[H_ + lp * HID + o];
                sum += cst;
            }
            #pragma unroll
            for (int o = 16; o > 0; o >>= 1)
                sum += __shfl_xor_sync(0xffffffffu, sum, o);
            if (lane == 0) out[b] = sum;
        }
        return;
    }

    // ======================= WORKER CTA =======================
    const int id = blockIdx.x;
    const int dc = id & 3, b = (id >> 2) & 15, l = id >> 6;
    const int dstart = dc * 128;
    float* sDn = reinterpret_cast<float*>(smdyn + SM_DN);
    float* sQn = reinterpret_cast<float*>(smdyn + SM_QN);
    int*   sHist = reinterpret_cast<int*>(smdyn + SM_HI);

    if (tid < NB) sHist[tid] = 0;

    // cp.async staging roles (coalesced: 16 lanes cover a 256B row)
    const int c16 = lane & 15;
    const int lane_hi = lane >> 4;
    const int rbase = wid * 16 + lane_hi * 8;
    const float* dbase0 = hs + ((size_t)(l * B_ + b) * S_ + QL) * H_;
    const float* qbase  = hs + (size_t)(l * B_ + b) * S_ * H_;

    auto issue_chunk = [&](int c, int s) {
        char* stA = smdyn + s * STAGE;
        char* stB = stA + 5120;
        #pragma unroll
        for (int j = 0; j < 8; j++) {
            int row = rbase + j;
            int dgl = dstart + row;
            cp16(stB + soff(row, c16 * 16),
                 dbase0 + (size_t)dgl * H_ + c * KC + c16 * 4, dgl < DL);
        }
        {   // Q rows 0..15 (256 threads -> one op each)
            int qr = tid >> 4, qc = tid & 15;
            cp16(stA + soff(qr, qc * 16),
                 qbase + (size_t)qr * H_ + c * KC + qc * 4, true);
        }
        if (tid < 64) {  // Q rows 16..19
            int qr = 16 + (tid >> 4), qc = tid & 15;
            cp16(stA + soff(qr, qc * 16),
                 qbase + (size_t)qr * H_ + c * KC + qc * 4, true);
        }
        cp_commit();
    };

    // MMA fragment geometry
    const int g = lane >> 2, tig = lane & 3;
    const int mi = wid & 1;
    const int n0 = (wid >> 1) * 32;
    const int ar0 = 16 * mi + g, ar1 = ar0 + 8;

    float acc[4][4];
    #pragma unroll
    for (int j = 0; j < 4; j++)
        #pragma unroll
        for (int k = 0; k < 4; k++) acc[j][k] = 0.f;
    float dn2[4] = {0.f, 0.f, 0.f, 0.f};
    float qn2a = 0.f, qn2b = 0.f;

    issue_chunk(0, 0);
    issue_chunk(1, 1);

    for (int c = 0; c < NCH; c++) {
        const int s = c & 1;
        if (c + 1 < NCH) cp_wait<1>(); else cp_wait<0>();
        __syncthreads();

        const char* stA = smdyn + s * STAGE;
        const char* stB = stA + 5120;
        #pragma unroll
        for (int kk = 0; kk < 4; kk++) {
            const int cb = kk * 64 + tig * 8;
            float2 fa0 = *reinterpret_cast<const float2*>(stA + soff(ar0, cb));
            float2 fa1 = *reinterpret_cast<const float2*>(stA + soff(ar1, cb));
            float2 fa2 = *reinterpret_cast<const float2*>(stA + soff(ar0, cb + 32));
            float2 fa3 = *reinterpret_cast<const float2*>(stA + soff(ar1, cb + 32));
            if (wid < 2) {   // q-norms: wid0 rows 0..15, wid1 rows 16..19
                qn2a += fa0.x * fa0.x + fa0.y * fa0.y + fa2.x * fa2.x + fa2.y * fa2.y;
                qn2b += fa1.x * fa1.x + fa1.y * fa1.y + fa3.x * fa3.x + fa3.y * fa3.y;
            }
            const uint32_t A0 = bfpack(fa0.x, fa0.y), A1 = bfpack(fa1.x, fa1.y);
            const uint32_t A2 = bfpack(fa2.x, fa2.y), A3 = bfpack(fa3.x, fa3.y);
            #pragma unroll
            for (int j = 0; j < 4; j++) {
                int brow = n0 + 8 * j + g;
                float2 fb0 = *reinterpret_cast<const float2*>(stB + soff(brow, cb));
                float2 fb1 = *reinterpret_cast<const float2*>(stB + soff(brow, cb + 32));
                if (mi == 0)
                    dn2[j] += fb0.x * fb0.x + fb0.y * fb0.y
                            + fb1.x * fb1.x + fb1.y * fb1.y;
                mma16816(acc[j], A0, A1, A2, A3,
                         bfpack(fb0.x, fb0.y), bfpack(fb1.x, fb1.y));
            }
        }
        __syncthreads();
        if (c + 2 < NCH) issue_chunk(c + 2, s);
    }

    // ---- norms -> smem (reduce over tig within quads) ----
    if (mi == 0) {
        #pragma unroll
        for (int j = 0; j < 4; j++) {
            float v = dn2[j];
            v += __shfl_xor_sync(0xffffffffu, v, 1);
            v += __shfl_xor_sync(0xffffffffu, v, 2);
            if (tig == 0) sDn[n0 + 8 * j + g] = sqrtf(v);
        }
    }
    if (wid == 0) {
        float va = qn2a, vb = qn2b;
        va += __shfl_xor_sync(0xffffffffu, va, 1);
        va += __shfl_xor_sync(0xffffffffu, va, 2);
        vb += __shfl_xor_sync(0xffffffffu, vb, 1);
        vb += __shfl_xor_sync(0xffffffffu, vb, 2);
        if (tig == 0) { sQn[g] = sqrtf(va); sQn[g + 8] = sqrtf(vb); }
    }
    if (wid == 1) {
        float va = qn2a;
        va += __shfl_xor_sync(0xffffffffu, va, 1);
        va += __shfl_xor_sync(0xffffffffu, va, 2);
        if (tig == 0 && g < QL - 16) sQn[16 + g] = sqrtf(va);
    }
    __syncthreads();

    // ---- epilogue: cosine -> bin -> warp-aggregated histogram ----
    {
        const int row0 = 16 * mi + g, row1 = row0 + 8;
        const int lc = tig * 2;
        const float qn0 = (row0 < QL) ? sQn[row0] : 1.f;
        const float qn1 = (row1 < QL) ? sQn[row1] : 1.f;
        #pragma unroll
        for (int j = 0; j < 4; j++) {
            const int col = n0 + 8 * j + lc;
            const float dn0 = sDn[col], dn1 = sDn[col + 1];
            #pragma unroll
            for (int e = 0; e < 4; e++) {
                const int rw  = (e < 2) ? row0 : row1;
                const float qn = (e < 2) ? qn0 : qn1;
                const int cl  = col + (e & 1);
                const float dn = (e & 1) ? dn1 : dn0;
                int idx = -1;
                if (rw < QL && dstart + cl < DL) {
                    float sim = acc[j][e] / fmaxf(qn * dn, EPSF);
                    float t = (sim + 1.0f) * 5.5f;
                    int bi = (int)floorf(t);
                    if (bi >= 0 && bi < NB) idx = bi;
                }
                unsigned m = __match_any_sync(0xffffffffu, idx);
                if (idx >= 0 && lane == (__ffs(m) - 1))
                    atomicAdd(&sHist[idx], __popc(m));
            }
        }
    }
    __syncthreads();
    if (tid < NB)
        g_hist[((l * B_ + b) * NDCH + dc) * NB + tid] = sHist[tid];
    __threadfence();
    __syncthreads();
    if (tid == 0) atomicAdd(&g_arrive, 1);
}

extern "C" void kernel_launch(void* const* d_in, const int* in_sizes, int n_in,
                              void* d_out, int out_size) {
    const float* hs     = (const float*)d_in[0];
    const float* W_hist = (const float*)d_in[1];
    const float* b_hist = (const float*)d_in[2];
    const float* W_comb = (const float*)d_in[3];
    const float* b_comb = (const float*)d_in[4];
    float* out = (float*)d_out;

    static bool attr_set = false;
    if (!attr_set) {
        cudaFuncSetAttribute(cedr_fused_kernel,
                             cudaFuncAttributeMaxDynamicSharedMemorySize, SM_SZ);
        attr_set = true;
    }
    cedr_fused_kernel<<<NWORK + 1, THR, SM_SZ>>>(hs, W_hist, b_hist, W_comb,
                                                 b_comb, out);
}